// round 7
// baseline (speedup 1.0000x reference)
#include <cuda_runtime.h>
#include <cstdint>
#include <math.h>

// ---------------------------------------------------------------------------
// Problem constants
// ---------------------------------------------------------------------------
#define TSEQ   2048
#define HID    2048
#define QDIM   4096   // 32 rope-heads * 128
#define KVDIM  1024   // 8 kv heads * 128
#define HD     128
#define NH16   16
#define NKV    8
#define HQ     32

// ---------------------------------------------------------------------------
// Static device scratch (no allocations allowed)
// ---------------------------------------------------------------------------
__device__ float g_q  [TSEQ * QDIM];
__device__ float g_k  [TSEQ * KVDIM];
__device__ float g_v  [TSEQ * KVDIM];
__device__ float g_qr [TSEQ * QDIM];
__device__ float g_kr [TSEQ * KVDIM];
__device__ float g_att[TSEQ * QDIM];
__device__ float g_wqt[QDIM * HID];
__device__ float g_wkt[KVDIM * HID];
__device__ float g_wvt[KVDIM * HID];
__device__ float g_wot[HID * QDIM];
__device__ float g_vt [KVDIM * TSEQ];

// ---------------------------------------------------------------------------
// tf32 helpers (base-target PTX only; no tcgen05 — ptxas targets compute_103)
// ---------------------------------------------------------------------------
__device__ __forceinline__ uint32_t f2tf32(float f) {
    uint32_t r;
    asm("cvt.rna.tf32.f32 %0, %1;" : "=r"(r) : "f"(f));
    return r;
}

__device__ __forceinline__ uint32_t smem_u32(const void* p) {
    uint32_t a;
    asm("{ .reg .u64 t; cvta.to.shared.u64 t, %1; cvt.u32.u64 %0, t; }"
        : "=r"(a) : "l"(p));
    return a;
}

__device__ __forceinline__ void mma_tf32(
    float& d0, float& d1, float& d2, float& d3,
    uint32_t a0, uint32_t a1, uint32_t a2, uint32_t a3,
    uint32_t b0, uint32_t b1)
{
    asm volatile(
        "mma.sync.aligned.m16n8k8.row.col.f32.tf32.tf32.f32 "
        "{%0,%1,%2,%3}, {%4,%5,%6,%7}, {%8,%9}, {%0,%1,%2,%3};"
        : "+f"(d0), "+f"(d1), "+f"(d2), "+f"(d3)
        : "r"(a0), "r"(a1), "r"(a2), "r"(a3), "r"(b0), "r"(b1));
}

__device__ __forceinline__ void cp16(uint32_t dst, const float* src) {
    asm volatile("cp.async.cg.shared.global [%0], [%1], 16;"
                 :: "r"(dst), "l"(src));
}
#define CP_COMMIT() asm volatile("cp.async.commit_group;" ::: "memory")
#define CP_WAIT0()  asm volatile("cp.async.wait_group 0;" ::: "memory")

// ---------------------------------------------------------------------------
// mma.sync tf32 GEMM: C[M,N] = A[M,K] @ B[N,K]^T   (unchanged from R4; passed)
// ---------------------------------------------------------------------------
#define BM 128
#define BN 128
#define BK 32
#define ASTR 36   // 32 + 4 pad (floats)

__global__ __launch_bounds__(256) void gemm_mma(
    const float* __restrict__ A, const float* __restrict__ B,
    float* __restrict__ C, int K, int lda, int ldb, int ldc,
    long long bsA, long long bsB, long long bsC, int bshift)
{
    __shared__ uint32_t As[BM][ASTR];
    __shared__ uint32_t Bs[BN][ASTR];

    const int z = blockIdx.z;
    A += (long long)z * bsA;
    B += (long long)(z >> bshift) * bsB;
    C += (long long)z * bsC;

    const int tid  = threadIdx.x;
    const int wid  = tid >> 5;
    const int lane = tid & 31;
    const int m0 = blockIdx.y * BM;
    const int n0 = blockIdx.x * BN;

    const int wm = (wid >> 2) * 64;
    const int wn = (wid & 3) * 32;
    const int g  = lane >> 2;
    const int t  = lane & 3;

    float acc[4][4][4];
#pragma unroll
    for (int mt = 0; mt < 4; mt++)
#pragma unroll
        for (int nt = 0; nt < 4; nt++)
#pragma unroll
            for (int r = 0; r < 4; r++) acc[mt][nt][r] = 0.0f;

    const int r0 = tid >> 3;
    const int c4 = (tid & 7) << 2;

    float4 pa[4], pb[4];
#pragma unroll
    for (int p = 0; p < 4; p++) {
        const int row = r0 + (p << 5);
        pa[p] = *(const float4*)(A + (size_t)(m0 + row) * lda + c4);
        pb[p] = *(const float4*)(B + (size_t)(n0 + row) * ldb + c4);
    }
#pragma unroll
    for (int p = 0; p < 4; p++) {
        const int row = r0 + (p << 5);
        As[row][c4 + 0] = f2tf32(pa[p].x);
        As[row][c4 + 1] = f2tf32(pa[p].y);
        As[row][c4 + 2] = f2tf32(pa[p].z);
        As[row][c4 + 3] = f2tf32(pa[p].w);
        Bs[row][c4 + 0] = f2tf32(pb[p].x);
        Bs[row][c4 + 1] = f2tf32(pb[p].y);
        Bs[row][c4 + 2] = f2tf32(pb[p].z);
        Bs[row][c4 + 3] = f2tf32(pb[p].w);
    }
    __syncthreads();

    const int nk = K >> 5;
    for (int kt = 0; kt < nk; kt++) {
        if (kt + 1 < nk) {
            const int k0 = (kt + 1) << 5;
#pragma unroll
            for (int p = 0; p < 4; p++) {
                const int row = r0 + (p << 5);
                pa[p] = *(const float4*)(A + (size_t)(m0 + row) * lda + k0 + c4);
                pb[p] = *(const float4*)(B + (size_t)(n0 + row) * ldb + k0 + c4);
            }
        }

#pragma unroll
        for (int ks = 0; ks < 4; ks++) {
            const int k = ks << 3;
            uint32_t af[4][4], bf[4][2];
#pragma unroll
            for (int mt = 0; mt < 4; mt++) {
                const int r = wm + mt * 16 + g;
                af[mt][0] = As[r    ][k + t];
                af[mt][1] = As[r + 8][k + t];
                af[mt][2] = As[r    ][k + t + 4];
                af[mt][3] = As[r + 8][k + t + 4];
            }
#pragma unroll
            for (int nt = 0; nt < 4; nt++) {
                const int r = wn + nt * 8 + g;
                bf[nt][0] = Bs[r][k + t];
                bf[nt][1] = Bs[r][k + t + 4];
            }
#pragma unroll
            for (int mt = 0; mt < 4; mt++)
#pragma unroll
                for (int nt = 0; nt < 4; nt++)
                    mma_tf32(acc[mt][nt][0], acc[mt][nt][1],
                             acc[mt][nt][2], acc[mt][nt][3],
                             af[mt][0], af[mt][1], af[mt][2], af[mt][3],
                             bf[nt][0], bf[nt][1]);
        }
        __syncthreads();

        if (kt + 1 < nk) {
#pragma unroll
            for (int p = 0; p < 4; p++) {
                const int row = r0 + (p << 5);
                As[row][c4 + 0] = f2tf32(pa[p].x);
                As[row][c4 + 1] = f2tf32(pa[p].y);
                As[row][c4 + 2] = f2tf32(pa[p].z);
                As[row][c4 + 3] = f2tf32(pa[p].w);
                Bs[row][c4 + 0] = f2tf32(pb[p].x);
                Bs[row][c4 + 1] = f2tf32(pb[p].y);
                Bs[row][c4 + 2] = f2tf32(pb[p].z);
                Bs[row][c4 + 3] = f2tf32(pb[p].w);
            }
            __syncthreads();
        }
    }

#pragma unroll
    for (int mt = 0; mt < 4; mt++) {
        const int row = m0 + wm + mt * 16 + g;
#pragma unroll
        for (int nt = 0; nt < 4; nt++) {
            const int col = n0 + wn + nt * 8 + 2 * t;
            *(float2*)(C + (size_t)row * ldc + col) =
                make_float2(acc[mt][nt][0], acc[mt][nt][1]);
            *(float2*)(C + (size_t)(row + 8) * ldc + col) =
                make_float2(acc[mt][nt][2], acc[mt][nt][3]);
        }
    }
}

// ---------------------------------------------------------------------------
// Fused flash attention (tf32 mma.sync).
// CTA = 128 queries x 1 head, 8 warps x 16 rows. Keys streamed in tiles of 64,
// double-buffered via cp.async. Q fragments in registers. P round-trips
// through warp-private SMEM to become the A-operand of P@V.
// Inputs Qr/Kr/Vt are pre-rounded to tf32 by their producers.
// ---------------------------------------------------------------------------
#define FQ 128
#define FK 64
#define KSTR 132               // 128 + 4 pad (words)
#define VSTR 68                // 64 + 4 pad
#define PSTR 68
#define KS_WORDS (FK * KSTR)   // 8448
#define VT_WORDS (HD * VSTR)   // 8704
#define PS_WORDS (FQ * PSTR)   // 8704
#define FA_SMEM ((2 * KS_WORDS + 2 * VT_WORDS + PS_WORDS) * 4)   // 172032 B

__device__ __forceinline__ void fa_load_kv(
    uint32_t ks_dst, uint32_t vt_dst,
    const float* __restrict__ Kr, const float* __restrict__ Vt,
    int k0, int kvh, int tid)
{
    // K tile: 64 keys x 128 d  (2048 float4)
#pragma unroll
    for (int c = 0; c < 8; c++) {
        const int idx = tid + 256 * c;
        const int row = idx >> 5, c4 = (idx & 31) << 2;
        cp16(ks_dst + (uint32_t)(row * KSTR + c4) * 4,
             Kr + (size_t)(k0 + row) * KVDIM + kvh * HD + c4);
    }
    // V^T tile: 128 d x 64 keys (2048 float4)
#pragma unroll
    for (int c = 0; c < 8; c++) {
        const int idx = tid + 256 * c;
        const int row = idx >> 4, c4 = (idx & 15) << 2;
        cp16(vt_dst + (uint32_t)(row * VSTR + c4) * 4,
             Vt + (size_t)(kvh * HD + row) * TSEQ + k0 + c4);
    }
}

__global__ __launch_bounds__(256) void flash_kernel(
    const float* __restrict__ Qr, const float* __restrict__ Kr,
    const float* __restrict__ Vt, float* __restrict__ O)
{
    extern __shared__ uint32_t fsm[];
    uint32_t* KsBase = fsm;
    uint32_t* VsBase = fsm + 2 * KS_WORDS;
    uint32_t* Ps     = fsm + 2 * KS_WORDS + 2 * VT_WORDS;

    const uint32_t smbase = smem_u32(fsm);
    const uint32_t ks_u = smbase;
    const uint32_t vt_u = smbase + 2 * KS_WORDS * 4;

    const int tid  = threadIdx.x;
    const int wid  = tid >> 5;
    const int lane = tid & 31;
    const int g = lane >> 2, t = lane & 3;
    const int q0 = blockIdx.x * FQ;
    const int h  = blockIdx.y;
    const int kvh = h >> 2;
    const int wrow = wid * 16;

    // Q fragments (rows wrow+g / wrow+g+8, all 16 k-chunks) — resident in regs
    uint32_t qf[16][4];
    {
        const float* qb  = Qr + (size_t)(q0 + wrow + g) * QDIM + h * HD;
        const float* qb8 = qb + 8 * QDIM;
#pragma unroll
        for (int kc = 0; kc < 16; kc++) {
            qf[kc][0] = __float_as_uint(qb [kc * 8 + t]);
            qf[kc][1] = __float_as_uint(qb8[kc * 8 + t]);
            qf[kc][2] = __float_as_uint(qb [kc * 8 + t + 4]);
            qf[kc][3] = __float_as_uint(qb8[kc * 8 + t + 4]);
        }
    }

    float o[16][4];
#pragma unroll
    for (int nt = 0; nt < 16; nt++)
#pragma unroll
        for (int r = 0; r < 4; r++) o[nt][r] = 0.0f;

    float m0 = -1e30f, m1 = -1e30f, l0 = 0.0f, l1 = 0.0f;
    const float scale = 0.08838834764831845f;   // 1/sqrt(128)

    fa_load_kv(ks_u, vt_u, Kr, Vt, 0, kvh, tid);
    CP_COMMIT();

    const int NKT = TSEQ / FK;   // 32
    for (int kt = 0; kt < NKT; kt++) {
        const int b = kt & 1;
        CP_WAIT0();
        __syncthreads();
        if (kt + 1 < NKT) {
            const int nb = b ^ 1;
            fa_load_kv(ks_u + nb * KS_WORDS * 4, vt_u + nb * VT_WORDS * 4,
                       Kr, Vt, (kt + 1) * FK, kvh, tid);
            CP_COMMIT();
        }

        const uint32_t* Ks = KsBase + b * KS_WORDS;
        const uint32_t* Vs = VsBase + b * VT_WORDS;

        // --- S = Q @ K^T  (128x64 per CTA, 16x64 per warp) ---
        float s[8][4];
#pragma unroll
        for (int nt = 0; nt < 8; nt++)
#pragma unroll
            for (int r = 0; r < 4; r++) s[nt][r] = 0.0f;

#pragma unroll
        for (int kc = 0; kc < 16; kc++) {
            const int k = kc * 8;
#pragma unroll
            for (int nt = 0; nt < 8; nt++) {
                const uint32_t* kr = Ks + (nt * 8 + g) * KSTR + k;
                mma_tf32(s[nt][0], s[nt][1], s[nt][2], s[nt][3],
                         qf[kc][0], qf[kc][1], qf[kc][2], qf[kc][3],
                         kr[t], kr[t + 4]);
            }
        }

        // --- online softmax (rows wrow+g and wrow+g+8; quad-local) ---
#pragma unroll
        for (int nt = 0; nt < 8; nt++)
#pragma unroll
            for (int r = 0; r < 4; r++) s[nt][r] *= scale;

        float mx0 = -1e30f, mx1 = -1e30f;
#pragma unroll
        for (int nt = 0; nt < 8; nt++) {
            mx0 = fmaxf(mx0, fmaxf(s[nt][0], s[nt][1]));
            mx1 = fmaxf(mx1, fmaxf(s[nt][2], s[nt][3]));
        }
        mx0 = fmaxf(mx0, __shfl_xor_sync(0xffffffffu, mx0, 1));
        mx0 = fmaxf(mx0, __shfl_xor_sync(0xffffffffu, mx0, 2));
        mx1 = fmaxf(mx1, __shfl_xor_sync(0xffffffffu, mx1, 1));
        mx1 = fmaxf(mx1, __shfl_xor_sync(0xffffffffu, mx1, 2));

        const float mn0 = fmaxf(m0, mx0);
        const float mn1 = fmaxf(m1, mx1);
        const float a0 = __expf(m0 - mn0);
        const float a1 = __expf(m1 - mn1);
        m0 = mn0; m1 = mn1;

        float sum0 = 0.0f, sum1 = 0.0f;
#pragma unroll
        for (int nt = 0; nt < 8; nt++) {
            s[nt][0] = __expf(s[nt][0] - mn0);
            s[nt][1] = __expf(s[nt][1] - mn0);
            s[nt][2] = __expf(s[nt][2] - mn1);
            s[nt][3] = __expf(s[nt][3] - mn1);
            sum0 += s[nt][0] + s[nt][1];
            sum1 += s[nt][2] + s[nt][3];
        }
        sum0 += __shfl_xor_sync(0xffffffffu, sum0, 1);
        sum0 += __shfl_xor_sync(0xffffffffu, sum0, 2);
        sum1 += __shfl_xor_sync(0xffffffffu, sum1, 1);
        sum1 += __shfl_xor_sync(0xffffffffu, sum1, 2);
        l0 = l0 * a0 + sum0;
        l1 = l1 * a1 + sum1;

        // rescale O accumulators
#pragma unroll
        for (int nt = 0; nt < 16; nt++) {
            o[nt][0] *= a0; o[nt][1] *= a0;
            o[nt][2] *= a1; o[nt][3] *= a1;
        }

        // --- P -> SMEM (warp-private rows; convert to tf32) ---
        __syncwarp();
#pragma unroll
        for (int nt = 0; nt < 8; nt++) {
            uint32_t* p0 = Ps + (wrow + g) * PSTR + nt * 8 + 2 * t;
            uint32_t* p1 = Ps + (wrow + g + 8) * PSTR + nt * 8 + 2 * t;
            *(uint2*)p0 = make_uint2(f2tf32(s[nt][0]), f2tf32(s[nt][1]));
            *(uint2*)p1 = make_uint2(f2tf32(s[nt][2]), f2tf32(s[nt][3]));
        }
        __syncwarp();

        // --- O += P @ V   (A = P rows from SMEM, B = V^T tile) ---
#pragma unroll
        for (int kc2 = 0; kc2 < 8; kc2++) {
            const int k2 = kc2 * 8;
            uint32_t af0 = Ps[(wrow + g) * PSTR + k2 + t];
            uint32_t af1 = Ps[(wrow + g + 8) * PSTR + k2 + t];
            uint32_t af2 = Ps[(wrow + g) * PSTR + k2 + t + 4];
            uint32_t af3 = Ps[(wrow + g + 8) * PSTR + k2 + t + 4];
#pragma unroll
            for (int nt = 0; nt < 16; nt++) {
                const uint32_t* vr = Vs + (nt * 8 + g) * VSTR + k2;
                mma_tf32(o[nt][0], o[nt][1], o[nt][2], o[nt][3],
                         af0, af1, af2, af3, vr[t], vr[t + 4]);
            }
        }
        __syncwarp();
    }

    // --- normalize + write ---
    const float i0 = 1.0f / l0;
    const float i1 = 1.0f / l1;
    const int row0 = q0 + wrow + g;
#pragma unroll
    for (int nt = 0; nt < 16; nt++) {
        const int col = h * HD + nt * 8 + 2 * t;
        *(float2*)(O + (size_t)row0 * QDIM + col) =
            make_float2(o[nt][0] * i0, o[nt][1] * i0);
        *(float2*)(O + (size_t)(row0 + 8) * QDIM + col) =
            make_float2(o[nt][2] * i1, o[nt][3] * i1);
    }
}

// ---------------------------------------------------------------------------
// Tiled transpose: out[C][R] = in[R][C]^T   (R, C multiples of 32)
// ROUND=1 additionally rounds values to tf32 (for V feeding the MMA B-operand)
// ---------------------------------------------------------------------------
template <int ROUND>
__global__ void transpose_kernel_t(const float* __restrict__ in,
                                   float* __restrict__ out, int R, int C)
{
    __shared__ float t[32][33];
    const int x = blockIdx.x * 32 + threadIdx.x;
    const int y0 = blockIdx.y * 32 + threadIdx.y;
#pragma unroll
    for (int j = 0; j < 32; j += 8)
        t[threadIdx.y + j][threadIdx.x] = in[(size_t)(y0 + j) * C + x];
    __syncthreads();
    const int x2 = blockIdx.y * 32 + threadIdx.x;
    const int y2 = blockIdx.x * 32 + threadIdx.y;
#pragma unroll
    for (int j = 0; j < 32; j += 8) {
        float v = t[threadIdx.x][threadIdx.y + j];
        if (ROUND) v = __uint_as_float(f2tf32(v));
        out[(size_t)(y2 + j) * R + x2] = v;
    }
}

// ---------------------------------------------------------------------------
// Q rmsnorm (over 256) + rope, output rounded to tf32. grid (TSEQ,16), 256 thr.
// ---------------------------------------------------------------------------
__global__ void qnorm_rope_kernel(
    const float* __restrict__ q, const float* __restrict__ w,
    const float* __restrict__ sinp, const float* __restrict__ cosp,
    float* __restrict__ out)
{
    const int t = blockIdx.x, h = blockIdx.y;
    const int tid = threadIdx.x;
    __shared__ float buf[256];
    __shared__ float red[8];

    float v = q[t * QDIM + h * 256 + tid];
    float ss = v * v;
#pragma unroll
    for (int o = 16; o > 0; o >>= 1) ss += __shfl_down_sync(0xffffffffu, ss, o);
    if ((tid & 31) == 0) red[tid >> 5] = ss;
    __syncthreads();
    if (tid < 8) {
        float s = red[tid];
#pragma unroll
        for (int o = 4; o > 0; o >>= 1) s += __shfl_down_sync(0xffu, s, o);
        if (tid == 0) red[0] = s;
    }
    __syncthreads();
    float inv = rsqrtf(red[0] * (1.0f / 256.0f) + 1e-6f);
    buf[tid] = v * inv * w[tid];
    __syncthreads();

    int sub = tid >> 7, d = tid & 127;
    const float* base = buf + (sub << 7);
    int j = (d < 64) ? d : d - 64;
    float c = cosp[t * 64 + j], s = sinp[t * 64 + j];
    float x1 = base[2 * j], x2 = base[2 * j + 1];
    float o = (d < 64) ? (x1 * c - x2 * s) : (x1 * s + x2 * c);
    out[t * QDIM + (h * 2 + sub) * HD + d] = __uint_as_float(f2tf32(o));
}

// ---------------------------------------------------------------------------
// K rmsnorm (over 128) + rope, output rounded to tf32. grid (TSEQ,8), 128 thr.
// ---------------------------------------------------------------------------
__global__ void knorm_rope_kernel(
    const float* __restrict__ k, const float* __restrict__ w,
    const float* __restrict__ sinp, const float* __restrict__ cosp,
    float* __restrict__ out)
{
    const int t = blockIdx.x, h = blockIdx.y;
    const int tid = threadIdx.x;
    __shared__ float buf[128];
    __shared__ float red[4];

    float v = k[t * KVDIM + h * HD + tid];
    float ss = v * v;
#pragma unroll
    for (int o = 16; o > 0; o >>= 1) ss += __shfl_down_sync(0xffffffffu, ss, o);
    if ((tid & 31) == 0) red[tid >> 5] = ss;
    __syncthreads();
    if (tid < 4) {
        float s = red[tid];
#pragma unroll
        for (int o = 2; o > 0; o >>= 1) s += __shfl_down_sync(0xfu, s, o);
        if (tid == 0) red[0] = s;
    }
    __syncthreads();
    float inv = rsqrtf(red[0] * (1.0f / 128.0f) + 1e-6f);
    buf[tid] = v * inv * w[tid];
    __syncthreads();

    int d = tid;
    int j = (d < 64) ? d : d - 64;
    float c = cosp[t * 64 + j], s = sinp[t * 64 + j];
    float x1 = buf[2 * j], x2 = buf[2 * j + 1];
    float o = (d < 64) ? (x1 * c - x2 * s) : (x1 * s + x2 * c);
    out[t * KVDIM + h * HD + d] = __uint_as_float(f2tf32(o));
}

// ---------------------------------------------------------------------------
// Launch
// ---------------------------------------------------------------------------
extern "C" void kernel_launch(void* const* d_in, const int* in_sizes, int n_in,
                              void* d_out, int out_size)
{
    const float* x    = (const float*)d_in[0];
    const float* Wq   = (const float*)d_in[1];
    const float* Wk   = (const float*)d_in[2];
    const float* Wv   = (const float*)d_in[3];
    const float* Wo   = (const float*)d_in[4];
    const float* qw   = (const float*)d_in[5];
    const float* kw   = (const float*)d_in[6];
    const float* sinp = (const float*)d_in[7];
    const float* cosp = (const float*)d_in[8];
    float* out = (float*)d_out;

    float *pq, *pk, *pv, *pqr, *pkr, *patt;
    float *pwqt, *pwkt, *pwvt, *pwot, *pvt;
    cudaGetSymbolAddress((void**)&pq,   g_q);
    cudaGetSymbolAddress((void**)&pk,   g_k);
    cudaGetSymbolAddress((void**)&pv,   g_v);
    cudaGetSymbolAddress((void**)&pqr,  g_qr);
    cudaGetSymbolAddress((void**)&pkr,  g_kr);
    cudaGetSymbolAddress((void**)&patt, g_att);
    cudaGetSymbolAddress((void**)&pwqt, g_wqt);
    cudaGetSymbolAddress((void**)&pwkt, g_wkt);
    cudaGetSymbolAddress((void**)&pwvt, g_wvt);
    cudaGetSymbolAddress((void**)&pwot, g_wot);
    cudaGetSymbolAddress((void**)&pvt,  g_vt);

    cudaFuncSetAttribute(flash_kernel,
                         cudaFuncAttributeMaxDynamicSharedMemorySize, FA_SMEM);

    dim3 tb(32, 8);
    // Weight transposes to [N,K] K-major (unrounded; gemm rounds internally)
    transpose_kernel_t<0><<<dim3(QDIM / 32, HID / 32), tb>>>(Wq, pwqt, HID, QDIM);
    transpose_kernel_t<0><<<dim3(KVDIM / 32, HID / 32), tb>>>(Wk, pwkt, HID, KVDIM);
    transpose_kernel_t<0><<<dim3(KVDIM / 32, HID / 32), tb>>>(Wv, pwvt, HID, KVDIM);
    transpose_kernel_t<0><<<dim3(HID / 32, QDIM / 32), tb>>>(Wo, pwot, QDIM, HID);

    // Projections
    gemm_mma<<<dim3(QDIM / BN, TSEQ / BM, 1), 256>>>(
        x, pwqt, pq, HID, HID, HID, QDIM, 0, 0, 0, 0);
    gemm_mma<<<dim3(KVDIM / BN, TSEQ / BM, 1), 256>>>(
        x, pwkt, pk, HID, HID, HID, KVDIM, 0, 0, 0, 0);
    gemm_mma<<<dim3(KVDIM / BN, TSEQ / BM, 1), 256>>>(
        x, pwvt, pv, HID, HID, HID, KVDIM, 0, 0, 0, 0);

    // Norm + rope (outputs tf32-rounded for the flash kernel)
    qnorm_rope_kernel<<<dim3(TSEQ, NH16), 256>>>(pq, qw, sinp, cosp, pqr);
    knorm_rope_kernel<<<dim3(TSEQ, NKV), 128>>>(pk, kw, sinp, cosp, pkr);

    // V^T (tf32-rounded) for the P@V B-operand
    transpose_kernel_t<1><<<dim3(KVDIM / 32, TSEQ / 32), tb>>>(pv, pvt, TSEQ, KVDIM);

    // Fused attention: softmax(QK^T/sqrt(d)) @ V
    flash_kernel<<<dim3(TSEQ / FQ, HQ), 256, FA_SMEM>>>(pqr, pkr, pvt, patt);

    // Output projection
    gemm_mma<<<dim3(HID / BN, TSEQ / BM, 1), 256>>>(
        patt, pwot, out, QDIM, QDIM, QDIM, HID, 0, 0, 0, 0);
}

// round 9
// speedup vs baseline: 2.0385x; 2.0385x over previous
#include <cuda_runtime.h>
#include <cuda_fp16.h>
#include <cstdint>
#include <math.h>

// ---------------------------------------------------------------------------
// Problem constants
// ---------------------------------------------------------------------------
#define TSEQ   2048
#define HID    2048
#define QDIM   4096   // 32 rope-heads * 128
#define KVDIM  1024   // 8 kv heads * 128
#define HD     128
#define NH16   16
#define NKV    8
#define HQ     32

// ---------------------------------------------------------------------------
// Static device scratch (no allocations allowed)
// ---------------------------------------------------------------------------
__device__ float  g_q  [TSEQ * QDIM];
__device__ float  g_k  [TSEQ * KVDIM];
__device__ float  g_v  [TSEQ * KVDIM];
__device__ float  g_qr [TSEQ * QDIM];
__device__ __half g_kr [TSEQ * KVDIM];
__device__ float  g_att[TSEQ * QDIM];
__device__ __half g_wqt[QDIM * HID];
__device__ __half g_wkt[KVDIM * HID];
__device__ __half g_wvt[KVDIM * HID];
__device__ __half g_wot[HID * QDIM];
__device__ __half g_vt [KVDIM * TSEQ];
__device__ float  g_s  [134217728];   // 32 heads * 2048 * 2048 fp32 = 512MB

// ---------------------------------------------------------------------------
// Helpers
// ---------------------------------------------------------------------------
__device__ __forceinline__ uint32_t pk_h2(float a, float b) {
    __half2 h = __floats2half2_rn(a, b);
    return *reinterpret_cast<uint32_t*>(&h);
}

__device__ __forceinline__ void mma_f16(
    float& d0, float& d1, float& d2, float& d3,
    uint32_t a0, uint32_t a1, uint32_t a2, uint32_t a3,
    uint32_t b0, uint32_t b1)
{
    asm volatile(
        "mma.sync.aligned.m16n8k16.row.col.f32.f16.f16.f32 "
        "{%0,%1,%2,%3}, {%4,%5,%6,%7}, {%8,%9}, {%0,%1,%2,%3};"
        : "+f"(d0), "+f"(d1), "+f"(d2), "+f"(d3)
        : "r"(a0), "r"(a1), "r"(a2), "r"(a3), "r"(b0), "r"(b1));
}

// ---------------------------------------------------------------------------
// fp16 mma.sync GEMM: C[M,N] = A[M,K] @ B[N,K]^T
// A row-major fp32 (converted to half2 on SMEM store); B row-major [N,K] half.
// 128x128 CTA tile, BK=32, 8 warps, warp tile 64x32 = 4x4 m16n8k16 fragments.
// Register prefetch of next K-chunk. Batched via blockIdx.z.
// M, N multiples of 128; K multiple of 32.
// ---------------------------------------------------------------------------
#define BM 128
#define BN 128
#define BK 32
#define AWS 20   // half2-word row stride: 16 data + 4 pad (conflict-free frags)

__global__ __launch_bounds__(256) void gemm_h(
    const float* __restrict__ A, const __half* __restrict__ B,
    float* __restrict__ C, int K, int lda, int ldb, int ldc,
    long long bsA, long long bsB, long long bsC, int bshift)
{
    __shared__ uint32_t As[BM][AWS];
    __shared__ uint32_t Bs[BN][AWS];

    const int z = blockIdx.z;
    A += (long long)z * bsA;
    B += (long long)(z >> bshift) * bsB;
    C += (long long)z * bsC;

    const int tid  = threadIdx.x;
    const int wid  = tid >> 5;
    const int lane = tid & 31;
    const int m0 = blockIdx.y * BM;
    const int n0 = blockIdx.x * BN;

    const int wm = (wid >> 2) * 64;   // warp M offset
    const int wn = (wid & 3) * 32;    // warp N offset
    const int g  = lane >> 2;
    const int t  = lane & 3;

    float acc[4][4][4];
#pragma unroll
    for (int mt = 0; mt < 4; mt++)
#pragma unroll
        for (int nt = 0; nt < 4; nt++)
#pragma unroll
            for (int r = 0; r < 4; r++) acc[mt][nt][r] = 0.0f;

    // A load: 32 rows/pass x 4 passes; 8 threads/row, float4 each
    const int ra = tid >> 3;
    const int ca = (tid & 7) << 2;        // float column
    // B load: 64 rows/pass x 2 passes; 4 threads/row, 8 halves (uint4) each
    const int rb = tid >> 2;
    const int cb = (tid & 3) << 3;        // half column

    float4 pa[4];
    uint4  pb[2];
#pragma unroll
    for (int p = 0; p < 4; p++)
        pa[p] = *(const float4*)(A + (size_t)(m0 + ra + (p << 5)) * lda + ca);
#pragma unroll
    for (int p = 0; p < 2; p++)
        pb[p] = *(const uint4*)(B + (size_t)(n0 + rb + (p << 6)) * ldb + cb);

#pragma unroll
    for (int p = 0; p < 4; p++) {
        const int r = ra + (p << 5);
        As[r][(ca >> 1) + 0] = pk_h2(pa[p].x, pa[p].y);
        As[r][(ca >> 1) + 1] = pk_h2(pa[p].z, pa[p].w);
    }
#pragma unroll
    for (int p = 0; p < 2; p++) {
        const int r = rb + (p << 6);
        Bs[r][(cb >> 1) + 0] = pb[p].x;
        Bs[r][(cb >> 1) + 1] = pb[p].y;
        Bs[r][(cb >> 1) + 2] = pb[p].z;
        Bs[r][(cb >> 1) + 3] = pb[p].w;
    }
    __syncthreads();

    const int nk = K >> 5;
    for (int kt = 0; kt < nk; kt++) {
        if (kt + 1 < nk) {
            const int k0 = (kt + 1) << 5;
#pragma unroll
            for (int p = 0; p < 4; p++)
                pa[p] = *(const float4*)(A + (size_t)(m0 + ra + (p << 5)) * lda + k0 + ca);
#pragma unroll
            for (int p = 0; p < 2; p++)
                pb[p] = *(const uint4*)(B + (size_t)(n0 + rb + (p << 6)) * ldb + k0 + cb);
        }

        // Two k16 chunks per tile
#pragma unroll
        for (int kc = 0; kc < 2; kc++) {
            const int kw = kc << 3;
            uint32_t af[4][4], bf[4][2];
#pragma unroll
            for (int mt = 0; mt < 4; mt++) {
                const int r = wm + mt * 16 + g;
                af[mt][0] = As[r    ][kw + t];
                af[mt][1] = As[r + 8][kw + t];
                af[mt][2] = As[r    ][kw + t + 4];
                af[mt][3] = As[r + 8][kw + t + 4];
            }
#pragma unroll
            for (int nt = 0; nt < 4; nt++) {
                const int r = wn + nt * 8 + g;
                bf[nt][0] = Bs[r][kw + t];
                bf[nt][1] = Bs[r][kw + t + 4];
            }
#pragma unroll
            for (int mt = 0; mt < 4; mt++)
#pragma unroll
                for (int nt = 0; nt < 4; nt++)
                    mma_f16(acc[mt][nt][0], acc[mt][nt][1],
                            acc[mt][nt][2], acc[mt][nt][3],
                            af[mt][0], af[mt][1], af[mt][2], af[mt][3],
                            bf[nt][0], bf[nt][1]);
        }
        __syncthreads();

        if (kt + 1 < nk) {
#pragma unroll
            for (int p = 0; p < 4; p++) {
                const int r = ra + (p << 5);
                As[r][(ca >> 1) + 0] = pk_h2(pa[p].x, pa[p].y);
                As[r][(ca >> 1) + 1] = pk_h2(pa[p].z, pa[p].w);
            }
#pragma unroll
            for (int p = 0; p < 2; p++) {
                const int r = rb + (p << 6);
                Bs[r][(cb >> 1) + 0] = pb[p].x;
                Bs[r][(cb >> 1) + 1] = pb[p].y;
                Bs[r][(cb >> 1) + 2] = pb[p].z;
                Bs[r][(cb >> 1) + 3] = pb[p].w;
            }
            __syncthreads();
        }
    }

    // Epilogue: c0,c1 at (row, 2t), c2,c3 at (row+8, 2t)
#pragma unroll
    for (int mt = 0; mt < 4; mt++) {
        const int row = m0 + wm + mt * 16 + g;
#pragma unroll
        for (int nt = 0; nt < 4; nt++) {
            const int col = n0 + wn + nt * 8 + 2 * t;
            *(float2*)(C + (size_t)row * ldc + col) =
                make_float2(acc[mt][nt][0], acc[mt][nt][1]);
            *(float2*)(C + (size_t)(row + 8) * ldc + col) =
                make_float2(acc[mt][nt][2], acc[mt][nt][3]);
        }
    }
}

// ---------------------------------------------------------------------------
// Tiled transpose fp32 -> fp16: out[C][R] = half(in[R][C]^T)
// ---------------------------------------------------------------------------
__global__ void transpose_h(const float* __restrict__ in,
                            __half* __restrict__ out, int R, int C)
{
    __shared__ float t[32][33];
    const int x = blockIdx.x * 32 + threadIdx.x;
    const int y0 = blockIdx.y * 32 + threadIdx.y;
#pragma unroll
    for (int j = 0; j < 32; j += 8)
        t[threadIdx.y + j][threadIdx.x] = in[(size_t)(y0 + j) * C + x];
    __syncthreads();
    const int x2 = blockIdx.y * 32 + threadIdx.x;
    const int y2 = blockIdx.x * 32 + threadIdx.y;
#pragma unroll
    for (int j = 0; j < 32; j += 8)
        out[(size_t)(y2 + j) * R + x2] = __float2half(t[threadIdx.x][threadIdx.y + j]);
}

// ---------------------------------------------------------------------------
// Row softmax with scale, in place (fp32). One warp per row of 2048.
// ---------------------------------------------------------------------------
__global__ __launch_bounds__(256) void softmax_kernel(float* __restrict__ S)
{
    const float scale = 0.08838834764831845f;  // 1/sqrt(128)
    const int row = blockIdx.x * 8 + (threadIdx.x >> 5);
    const int lane = threadIdx.x & 31;
    float* p = S + (size_t)row * 2048 + lane * 4;

    float4 v[16];
#pragma unroll
    for (int w = 0; w < 16; w++) v[w] = *(const float4*)(p + w * 128);

    float m = -1e30f;
#pragma unroll
    for (int w = 0; w < 16; w++)
        m = fmaxf(m, fmaxf(fmaxf(v[w].x, v[w].y), fmaxf(v[w].z, v[w].w)));
#pragma unroll
    for (int o = 16; o > 0; o >>= 1)
        m = fmaxf(m, __shfl_xor_sync(0xffffffffu, m, o));

    const float ms = m * scale;
    float sum = 0.0f;
#pragma unroll
    for (int w = 0; w < 16; w++) {
        v[w].x = __expf(fmaf(v[w].x, scale, -ms));
        v[w].y = __expf(fmaf(v[w].y, scale, -ms));
        v[w].z = __expf(fmaf(v[w].z, scale, -ms));
        v[w].w = __expf(fmaf(v[w].w, scale, -ms));
        sum += v[w].x + v[w].y + v[w].z + v[w].w;
    }
#pragma unroll
    for (int o = 16; o > 0; o >>= 1)
        sum += __shfl_xor_sync(0xffffffffu, sum, o);

    const float inv = 1.0f / sum;
#pragma unroll
    for (int w = 0; w < 16; w++) {
        v[w].x *= inv; v[w].y *= inv; v[w].z *= inv; v[w].w *= inv;
        *(float4*)(p + w * 128) = v[w];
    }
}

// ---------------------------------------------------------------------------
// Q rmsnorm (over 256) + rope (fp32 out). grid (TSEQ,16), 256 threads.
// ---------------------------------------------------------------------------
__global__ void qnorm_rope_kernel(
    const float* __restrict__ q, const float* __restrict__ w,
    const float* __restrict__ sinp, const float* __restrict__ cosp,
    float* __restrict__ out)
{
    const int t = blockIdx.x, h = blockIdx.y;
    const int tid = threadIdx.x;
    __shared__ float buf[256];
    __shared__ float red[8];

    float v = q[t * QDIM + h * 256 + tid];
    float ss = v * v;
#pragma unroll
    for (int o = 16; o > 0; o >>= 1) ss += __shfl_down_sync(0xffffffffu, ss, o);
    if ((tid & 31) == 0) red[tid >> 5] = ss;
    __syncthreads();
    if (tid < 8) {
        float s = red[tid];
#pragma unroll
        for (int o = 4; o > 0; o >>= 1) s += __shfl_down_sync(0xffu, s, o);
        if (tid == 0) red[0] = s;
    }
    __syncthreads();
    float inv = rsqrtf(red[0] * (1.0f / 256.0f) + 1e-6f);
    buf[tid] = v * inv * w[tid];
    __syncthreads();

    int sub = tid >> 7, d = tid & 127;
    const float* base = buf + (sub << 7);
    int j = (d < 64) ? d : d - 64;
    float c = cosp[t * 64 + j], s = sinp[t * 64 + j];
    float x1 = base[2 * j], x2 = base[2 * j + 1];
    float o = (d < 64) ? (x1 * c - x2 * s) : (x1 * s + x2 * c);
    out[t * QDIM + (h * 2 + sub) * HD + d] = o;
}

// ---------------------------------------------------------------------------
// K rmsnorm (over 128) + rope, fp16 out. grid (TSEQ,8), 128 threads.
// ---------------------------------------------------------------------------
__global__ void knorm_rope_kernel(
    const float* __restrict__ k, const float* __restrict__ w,
    const float* __restrict__ sinp, const float* __restrict__ cosp,
    __half* __restrict__ out)
{
    const int t = blockIdx.x, h = blockIdx.y;
    const int tid = threadIdx.x;
    __shared__ float buf[128];
    __shared__ float red[4];

    float v = k[t * KVDIM + h * HD + tid];
    float ss = v * v;
#pragma unroll
    for (int o = 16; o > 0; o >>= 1) ss += __shfl_down_sync(0xffffffffu, ss, o);
    if ((tid & 31) == 0) red[tid >> 5] = ss;
    __syncthreads();
    if (tid < 4) {
        float s = red[tid];
#pragma unroll
        for (int o = 2; o > 0; o >>= 1) s += __shfl_down_sync(0xfu, s, o);
        if (tid == 0) red[0] = s;
    }
    __syncthreads();
    float inv = rsqrtf(red[0] * (1.0f / 128.0f) + 1e-6f);
    buf[tid] = v * inv * w[tid];
    __syncthreads();

    int d = tid;
    int j = (d < 64) ? d : d - 64;
    float c = cosp[t * 64 + j], s = sinp[t * 64 + j];
    float x1 = buf[2 * j], x2 = buf[2 * j + 1];
    float o = (d < 64) ? (x1 * c - x2 * s) : (x1 * s + x2 * c);
    out[t * KVDIM + h * HD + d] = __float2half(o);
}

// ---------------------------------------------------------------------------
// Launch
// ---------------------------------------------------------------------------
extern "C" void kernel_launch(void* const* d_in, const int* in_sizes, int n_in,
                              void* d_out, int out_size)
{
    const float* x    = (const float*)d_in[0];
    const float* Wq   = (const float*)d_in[1];
    const float* Wk   = (const float*)d_in[2];
    const float* Wv   = (const float*)d_in[3];
    const float* Wo   = (const float*)d_in[4];
    const float* qw   = (const float*)d_in[5];
    const float* kw   = (const float*)d_in[6];
    const float* sinp = (const float*)d_in[7];
    const float* cosp = (const float*)d_in[8];
    float* out = (float*)d_out;

    float *pq, *pk, *pv, *pqr, *patt, *ps;
    __half *pkr, *pwqt, *pwkt, *pwvt, *pwot, *pvt;
    cudaGetSymbolAddress((void**)&pq,   g_q);
    cudaGetSymbolAddress((void**)&pk,   g_k);
    cudaGetSymbolAddress((void**)&pv,   g_v);
    cudaGetSymbolAddress((void**)&pqr,  g_qr);
    cudaGetSymbolAddress((void**)&pkr,  g_kr);
    cudaGetSymbolAddress((void**)&patt, g_att);
    cudaGetSymbolAddress((void**)&pwqt, g_wqt);
    cudaGetSymbolAddress((void**)&pwkt, g_wkt);
    cudaGetSymbolAddress((void**)&pwvt, g_wvt);
    cudaGetSymbolAddress((void**)&pwot, g_wot);
    cudaGetSymbolAddress((void**)&pvt,  g_vt);
    cudaGetSymbolAddress((void**)&ps,   g_s);

    dim3 tb(32, 8);
    // Weight transposes to [N,K] half
    transpose_h<<<dim3(QDIM / 32, HID / 32), tb>>>(Wq, pwqt, HID, QDIM);
    transpose_h<<<dim3(KVDIM / 32, HID / 32), tb>>>(Wk, pwkt, HID, KVDIM);
    transpose_h<<<dim3(KVDIM / 32, HID / 32), tb>>>(Wv, pwvt, HID, KVDIM);
    transpose_h<<<dim3(HID / 32, QDIM / 32), tb>>>(Wo, pwot, QDIM, HID);

    // Projections (A fp32, B fp16)
    gemm_h<<<dim3(QDIM / BN, TSEQ / BM, 1), 256>>>(
        x, pwqt, pq, HID, HID, HID, QDIM, 0, 0, 0, 0);
    gemm_h<<<dim3(KVDIM / BN, TSEQ / BM, 1), 256>>>(
        x, pwkt, pk, HID, HID, HID, KVDIM, 0, 0, 0, 0);
    gemm_h<<<dim3(KVDIM / BN, TSEQ / BM, 1), 256>>>(
        x, pwvt, pv, HID, HID, HID, KVDIM, 0, 0, 0, 0);

    // Norm + rope (K output fp16 -> B operand of S gemm)
    qnorm_rope_kernel<<<dim3(TSEQ, NH16), 256>>>(pq, qw, sinp, cosp, pqr);
    knorm_rope_kernel<<<dim3(TSEQ, NKV), 128>>>(pk, kw, sinp, cosp, pkr);

    // V^T (fp16) for PV gemm B operand
    transpose_h<<<dim3(KVDIM / 32, TSEQ / 32), tb>>>(pv, pvt, TSEQ, KVDIM);

    // S = Q K^T per head (raw logits), batched over 32 heads
    gemm_h<<<dim3(TSEQ / BN, TSEQ / BM, HQ), 256>>>(
        pqr, pkr, ps, HD, QDIM, KVDIM, TSEQ,
        (long long)HD, (long long)HD, (long long)TSEQ * TSEQ, 2);

    // softmax rows (scale folded in), fp32 in place
    softmax_kernel<<<(HQ * TSEQ) / 8, 256>>>(ps);

    // O = P V per head
    gemm_h<<<dim3(HD / BN, TSEQ / BM, HQ), 256>>>(
        ps, pvt, patt, TSEQ, TSEQ, TSEQ, QDIM,
        (long long)TSEQ * TSEQ, (long long)HD * TSEQ, (long long)HD, 2);

    // Output projection
    gemm_h<<<dim3(HID / BN, TSEQ / BM, 1), 256>>>(
        patt, pwot, out, QDIM, QDIM, QDIM, HID, 0, 0, 0, 0);
}